// round 4
// baseline (speedup 1.0000x reference)
#include <cuda_runtime.h>
#include <math.h>

#define BB   2
#define TT   2048
#define HID  1024
#define HH   16
#define HKV  4
#define MROWS  (BB*TT)          // 4096
#define QCOLS  1024
#define KVCOLS 512
#define NCHUNK 32               // T / 64

// ---------------- scratch (device globals; no allocation) ------------------
__device__ float g_q[MROWS * QCOLS];       // relu(hs@Wq)
__device__ float g_kv[MROWS * KVCOLS];     // [relu(hs@Wk)->ke | hs@Wv]
__device__ float g_lg[MROWS * 256];        // log decay -> then be=exp(b)*0.125
__device__ float g_oattn[MROWS * QCOLS];   // normed attention out
__device__ float g_Wkv[HID * KVCOLS];      // concat(Wk, Wv)
__device__ float g_Wg1p[HID * 128];        // Wg1 zero-padded to 128 cols
__device__ float g_glow[MROWS * 128];      // hs @ Wg1p
__device__ float g_S[8 * NCHUNK * 64 * 64];// per-chunk entering states
__device__ float g_dl[8 * NCHUNK * 64];    // exp(b_last)

// ---------------- tf32 mma helpers -----------------------------------------
__device__ __forceinline__ unsigned f2tf(float x) {
    unsigned r; asm("cvt.rna.tf32.f32 %0, %1;" : "=r"(r) : "f"(x)); return r;
}
__device__ __forceinline__ void mma_tf32(float* c, const unsigned* a,
                                         unsigned b0, unsigned b1) {
    asm volatile(
        "mma.sync.aligned.m16n8k8.row.col.f32.tf32.tf32.f32 "
        "{%0,%1,%2,%3},{%4,%5,%6,%7},{%8,%9},{%0,%1,%2,%3};"
        : "+f"(c[0]), "+f"(c[1]), "+f"(c[2]), "+f"(c[3])
        : "r"(a[0]), "r"(a[1]), "r"(a[2]), "r"(a[3]), "r"(b0), "r"(b1));
}

// ---------------- tf32 tensor-core GEMM: C = act(A[M,K] @ B[K,N]) ----------
#define GBM 128
#define GBN 128
#define GBK 16
#define LDA 20
#define LDB 136

__global__ void __launch_bounds__(256) mma_gemm(const float* __restrict__ A,
                                                const float* __restrict__ B,
                                                float* __restrict__ C,
                                                int M, int N, int K,
                                                int relu_limit) {
    __shared__ unsigned As[2][GBM][LDA];
    __shared__ unsigned Bs[2][GBK][LDB];

    const int tid  = threadIdx.x;
    const int lane = tid & 31;
    const int warp = tid >> 5;
    const int row0 = blockIdx.y * GBM;
    const int col0 = blockIdx.x * GBN;
    const int wm = (warp & 3) * 32;
    const int wn = (warp >> 2) * 64;

    const int ar = tid >> 1, ak = (tid & 1) * 8;
    const int bk = tid >> 4, bn = (tid & 15) * 8;

    float acc[2][8][4];
    #pragma unroll
    for (int i = 0; i < 2; i++)
        #pragma unroll
        for (int j = 0; j < 8; j++)
            #pragma unroll
            for (int l = 0; l < 4; l++) acc[i][j][l] = 0.f;

    float4 ag0, ag1, bg0, bg1;

    auto LDGT = [&](int kt) {
        const float* ap = A + (size_t)(row0 + ar) * K + kt * GBK + ak;
        ag0 = *(const float4*)ap;
        ag1 = *(const float4*)(ap + 4);
        const float* bp = B + (size_t)(kt * GBK + bk) * N + col0 + bn;
        bg0 = *(const float4*)bp;
        bg1 = *(const float4*)(bp + 4);
    };
    auto STST = [&](int bu) {
        *(uint4*)&As[bu][ar][ak]     = make_uint4(f2tf(ag0.x), f2tf(ag0.y), f2tf(ag0.z), f2tf(ag0.w));
        *(uint4*)&As[bu][ar][ak + 4] = make_uint4(f2tf(ag1.x), f2tf(ag1.y), f2tf(ag1.z), f2tf(ag1.w));
        *(uint4*)&Bs[bu][bk][bn]     = make_uint4(f2tf(bg0.x), f2tf(bg0.y), f2tf(bg0.z), f2tf(bg0.w));
        *(uint4*)&Bs[bu][bk][bn + 4] = make_uint4(f2tf(bg1.x), f2tf(bg1.y), f2tf(bg1.z), f2tf(bg1.w));
    };
    auto COMP = [&](int bu) {
        #pragma unroll
        for (int ks = 0; ks < 2; ks++) {
            unsigned a[2][4];
            #pragma unroll
            for (int mt = 0; mt < 2; mt++) {
                int r  = wm + mt * 16 + (lane >> 2);
                int cb = ks * 8 + (lane & 3);
                a[mt][0] = As[bu][r][cb];
                a[mt][1] = As[bu][r + 8][cb];
                a[mt][2] = As[bu][r][cb + 4];
                a[mt][3] = As[bu][r + 8][cb + 4];
            }
            #pragma unroll
            for (int nt = 0; nt < 8; nt++) {
                int nc = wn + nt * 8 + (lane >> 2);
                unsigned b0 = Bs[bu][ks * 8 + (lane & 3)][nc];
                unsigned b1 = Bs[bu][ks * 8 + (lane & 3) + 4][nc];
                mma_tf32(acc[0][nt], a[0], b0, b1);
                mma_tf32(acc[1][nt], a[1], b0, b1);
            }
        }
    };

    const int NTILES = K / GBK;
    LDGT(0); STST(0);
    __syncthreads();
    for (int kt = 0; kt < NTILES; kt++) {
        if (kt + 1 < NTILES) LDGT(kt + 1);
        COMP(kt & 1);
        if (kt + 1 < NTILES) STST((kt + 1) & 1);
        __syncthreads();
    }

    #pragma unroll
    for (int mt = 0; mt < 2; mt++) {
        #pragma unroll
        for (int nt = 0; nt < 8; nt++) {
            int r  = row0 + wm + mt * 16 + (lane >> 2);
            int cc = col0 + wn + nt * 8 + (lane & 3) * 2;
            float v0 = acc[mt][nt][0], v1 = acc[mt][nt][1];
            float v2 = acc[mt][nt][2], v3 = acc[mt][nt][3];
            if (cc < relu_limit) {
                v0 = fmaxf(v0, 0.f); v1 = fmaxf(v1, 0.f);
                v2 = fmaxf(v2, 0.f); v3 = fmaxf(v3, 0.f);
            }
            *(float2*)&C[(size_t)r * N + cc]       = make_float2(v0, v1);
            *(float2*)&C[(size_t)(r + 8) * N + cc] = make_float2(v2, v3);
        }
    }
}

// ---------------- weight prep: g_Wkv = [Wk|Wv]; g_Wg1p = pad(Wg1) ----------
__global__ void concat_w(const float* __restrict__ Wk, const float* __restrict__ Wv,
                         const float* __restrict__ Wg1) {
    int i = blockIdx.x * 256 + threadIdx.x;
    if (i < HID * KVCOLS) {
        int k = i >> 9, n = i & 511;
        g_Wkv[i] = (n < 256) ? Wk[k * 256 + n] : Wv[k * 256 + n - 256];
    }
    if (i < HID * 128) {
        int k = i >> 7, n = i & 127;
        g_Wg1p[i] = (n < 16) ? Wg1[k * 16 + n] : 0.f;
    }
}

// ---------------- gate stage 2: lg = logsigmoid(glow@Wg2 + b)/16 -----------
__global__ void __launch_bounds__(256) gate2_kernel(const float* __restrict__ Wg2,
                                                    const float* __restrict__ bg2) {
    __shared__ float w2[16][256];
    const int tid = threadIdx.x;
    #pragma unroll
    for (int i = tid; i < 4096; i += 256)
        w2[i >> 8][i & 255] = Wg2[i];
    __syncthreads();

    const int c = tid;
    const float bias = bg2[c];
    const int row0 = blockIdx.x * 4;
    #pragma unroll
    for (int rr = 0; rr < 4; rr++) {
        const int row = row0 + rr;
        const float* gl = g_glow + (size_t)row * 128;
        float x = bias;
        #pragma unroll
        for (int j = 0; j < 16; j++) x += gl[j] * w2[j][c];
        float ls = fminf(x, 0.f) - log1pf(__expf(-fabsf(x)));
        g_lg[(size_t)row * 256 + c] = ls * 0.0625f;
    }
}

// ---------------- Phase A: cumsum; be=exp(b)/8 in place; scale k -----------
__global__ void __launch_bounds__(64) phaseA_kernel() {
    const int c   = blockIdx.x & 31;
    const int grp = blockIdx.x >> 5;
    const int b = grp >> 2, hk = grp & 3;
    const int d = threadIdx.x;
    float bacc = 0.f;
    const size_t row0 = (size_t)b * TT + c * 64;
    for (int t = 0; t < 64; t++) {
        const size_t r = row0 + t;
        bacc += g_lg[r * 256 + hk * 64 + d];
        g_lg[r * 256 + hk * 64 + d] = __expf(bacc) * 0.125f;  // be (q scale folded)
        g_kv[r * 512 + hk * 64 + d] *= __expf(-bacc);
    }
    g_dl[(grp * 32 + c) * 64 + d] = __expf(bacc);
}

// ---------------- Phase B: propagate states across chunks ------------------
__global__ void __launch_bounds__(128) phaseB_kernel() {
    const int grp = blockIdx.x >> 3;
    const int vc  = blockIdx.x & 7;
    const int b = grp >> 2, hk = grp & 3;
    const int tid = threadIdx.x;
    const int v  = tid & 7;
    const int kg = tid >> 3;
    __shared__ float ke_s[64][64];
    __shared__ float v_s[64][8];
    float S0 = 0.f, S1 = 0.f, S2 = 0.f, S3 = 0.f;

    for (int c = 0; c < NCHUNK; c++) {
        const size_t row0 = (size_t)b * TT + c * 64;
        __syncthreads();
        #pragma unroll
        for (int i = tid; i < 64 * 16; i += 128) {
            int t = i >> 4, dq = i & 15;
            ((float4*)ke_s[t])[dq] = *(const float4*)&g_kv[(row0 + t) * 512 + hk * 64 + dq * 4];
        }
        {
            int t = tid >> 1, q4 = tid & 1;
            ((float4*)v_s[t])[q4] = *(const float4*)&g_kv[(row0 + t) * 512 + 256 + hk * 64 + vc * 8 + q4 * 4];
        }
        __syncthreads();

        const size_t sb_ = ((size_t)(grp * 32 + c) * 64 + kg * 4) * 64 + vc * 8 + v;
        g_S[sb_]       = S0;
        g_S[sb_ + 64]  = S1;
        g_S[sb_ + 128] = S2;
        g_S[sb_ + 192] = S3;

        #pragma unroll 4
        for (int t = 0; t < 64; t++) {
            const float4 kk = ((const float4*)ke_s[t])[kg];
            const float  vv = v_s[t][v];
            S0 = fmaf(kk.x, vv, S0);
            S1 = fmaf(kk.y, vv, S1);
            S2 = fmaf(kk.z, vv, S2);
            S3 = fmaf(kk.w, vv, S3);
        }
        const float4 dl4 = *(const float4*)&g_dl[(grp * 32 + c) * 64 + kg * 4];
        S0 *= dl4.x; S1 *= dl4.y; S2 *= dl4.z; S3 *= dl4.w;
    }
}

// ---------------- Phase C: tensor-core intra-chunk + inter + RMSNorm -------
// Block = (grp, head, chunk). 8 warps: 4 m-warps x 2 n-warps, warp tile 16x32.
// O = tril(qe@ke^T)@v + qe@S_c, RMSNorm fused in epilogue.
#define PC_LD 65
__global__ void __launch_bounds__(256) phaseC_kernel(const float* __restrict__ gnw) {
    extern __shared__ unsigned smc[];
    unsigned* qe  = smc;                 // [64][65]  qe (tf32)
    unsigned* keT = smc + 64 * PC_LD;    // [64][65]  ke^T, then masked A
    unsigned* vs  = smc + 2 * 64 * PC_LD;// [64][65]  v  ([s][d])
    unsigned* Ss  = smc + 3 * 64 * PC_LD;// [64][65]  S  ([d][d2])
    __shared__ float rs[64][2];

    const int c   = blockIdx.x & 31;
    const int h   = (blockIdx.x >> 5) & 3;
    const int grp = blockIdx.x >> 7;
    const int b = grp >> 2, hk = grp & 3;
    const int tid  = threadIdx.x;
    const int lane = tid & 31;
    const int warp = tid >> 5;
    const int wm = (warp & 3) * 16;
    const int wn = (warp >> 2) * 32;
    const int gr = lane >> 2, gc = lane & 3;
    const size_t row0 = (size_t)b * TT + c * 64;

    // stage (qe scaled by be; keT transposed)
    for (int i = tid; i < 4096; i += 256) {
        int t = i >> 6, d = i & 63;
        float qv = g_q[(row0 + t) * 1024 + hk * 256 + h * 64 + d]
                 * g_lg[(row0 + t) * 256 + hk * 64 + d];
        qe [t * PC_LD + d] = f2tf(qv);
        keT[d * PC_LD + t] = f2tf(g_kv[(row0 + t) * 512 + hk * 64 + d]);
        vs [t * PC_LD + d] = f2tf(g_kv[(row0 + t) * 512 + 256 + hk * 64 + d]);
        Ss [t * PC_LD + d] = f2tf(g_S[((size_t)(grp * 32 + c) * 64 + t) * 64 + d]);
    }
    __syncthreads();

    // A = qe @ ke^T   (k = d; B operand keT[k=d][n=s])
    float accA[4][4];
    #pragma unroll
    for (int j = 0; j < 4; j++)
        #pragma unroll
        for (int l = 0; l < 4; l++) accA[j][l] = 0.f;
    const int rm = wm + gr;
    #pragma unroll
    for (int ks = 0; ks < 8; ks++) {
        int cb = ks * 8 + gc;
        unsigned a[4];
        a[0] = qe[rm * PC_LD + cb];
        a[1] = qe[(rm + 8) * PC_LD + cb];
        a[2] = qe[rm * PC_LD + cb + 4];
        a[3] = qe[(rm + 8) * PC_LD + cb + 4];
        #pragma unroll
        for (int nt = 0; nt < 4; nt++) {
            int nc = wn + nt * 8 + gr;
            unsigned b0 = keT[cb * PC_LD + nc];
            unsigned b1 = keT[(cb + 4) * PC_LD + nc];
            mma_tf32(accA[nt], a, b0, b1);
        }
    }
    __syncthreads();
    // causal mask + store A (tf32) over keT
    #pragma unroll
    for (int nt = 0; nt < 4; nt++) {
        int s0 = wn + nt * 8 + gc * 2;
        keT[rm * PC_LD + s0]           = f2tf(s0     <= rm     ? accA[nt][0] : 0.f);
        keT[rm * PC_LD + s0 + 1]       = f2tf(s0 + 1 <= rm     ? accA[nt][1] : 0.f);
        keT[(rm + 8) * PC_LD + s0]     = f2tf(s0     <= rm + 8 ? accA[nt][2] : 0.f);
        keT[(rm + 8) * PC_LD + s0 + 1] = f2tf(s0 + 1 <= rm + 8 ? accA[nt][3] : 0.f);
    }
    __syncthreads();

    // O = A @ v + qe @ S
    float acc[4][4];
    #pragma unroll
    for (int j = 0; j < 4; j++)
        #pragma unroll
        for (int l = 0; l < 4; l++) acc[j][l] = 0.f;
    #pragma unroll
    for (int ks = 0; ks < 8; ks++) {
        int cb = ks * 8 + gc;
        unsigned a[4];
        a[0] = keT[rm * PC_LD + cb];
        a[1] = keT[(rm + 8) * PC_LD + cb];
        a[2] = keT[rm * PC_LD + cb + 4];
        a[3] = keT[(rm + 8) * PC_LD + cb + 4];
        #pragma unroll
        for (int nt = 0; nt < 4; nt++) {
            int nc = wn + nt * 8 + gr;
            unsigned b0 = vs[cb * PC_LD + nc];
            unsigned b1 = vs[(cb + 4) * PC_LD + nc];
            mma_tf32(acc[nt], a, b0, b1);
        }
    }
    #pragma unroll
    for (int ks = 0; ks < 8; ks++) {
        int cb = ks * 8 + gc;
        unsigned a[4];
        a[0] = qe[rm * PC_LD + cb];
        a[1] = qe[(rm + 8) * PC_LD + cb];
        a[2] = qe[rm * PC_LD + cb + 4];
        a[3] = qe[(rm + 8) * PC_LD + cb + 4];
        #pragma unroll
        for (int nt = 0; nt < 4; nt++) {
            int nc = wn + nt * 8 + gr;
            unsigned b0 = Ss[cb * PC_LD + nc];
            unsigned b1 = Ss[(cb + 4) * PC_LD + nc];
            mma_tf32(acc[nt], a, b0, b1);
        }
    }

    // fused RMSNorm over the 64 cols of each row
    float ss0 = 0.f, ss1 = 0.f;
    #pragma unroll
    for (int nt = 0; nt < 4; nt++) {
        ss0 += acc[nt][0] * acc[nt][0] + acc[nt][1] * acc[nt][1];
        ss1 += acc[nt][2] * acc[nt][2] + acc[nt][3] * acc[nt][3];
    }
    ss0 += __shfl_xor_sync(0xffffffffu, ss0, 1);
    ss0 += __shfl_xor_sync(0xffffffffu, ss0, 2);
    ss1 += __shfl_xor_sync(0xffffffffu, ss1, 1);
    ss1 += __shfl_xor_sync(0xffffffffu, ss1, 2);
    if (gc == 0) {
        rs[rm][warp >> 2]     = ss0;
        rs[rm + 8][warp >> 2] = ss1;
    }
    __syncthreads();
    float r0 = rsqrtf((rs[rm][0] + rs[rm][1]) * (1.f / 64.f) + 1e-6f);
    float r1 = rsqrtf((rs[rm + 8][0] + rs[rm + 8][1]) * (1.f / 64.f) + 1e-6f);

    const size_t ob = (row0)*1024 + (size_t)(hk * 4 + h) * 64;
    #pragma unroll
    for (int nt = 0; nt < 4; nt++) {
        int cc = wn + nt * 8 + gc * 2;
        float gw0 = gnw[cc], gw1 = gnw[cc + 1];
        *(float2*)&g_oattn[ob + (size_t)rm * 1024 + cc] =
            make_float2(acc[nt][0] * r0 * gw0, acc[nt][1] * r0 * gw1);
        *(float2*)&g_oattn[ob + (size_t)(rm + 8) * 1024 + cc] =
            make_float2(acc[nt][2] * r1 * gw0, acc[nt][3] * r1 * gw1);
    }
}

// ---------------- launch -----------------------------------------------------
extern "C" void kernel_launch(void* const* d_in, const int* in_sizes, int n_in,
                              void* d_out, int out_size) {
    const float* hs  = (const float*)d_in[0];
    const float* Wq  = (const float*)d_in[1];
    const float* Wk  = (const float*)d_in[2];
    const float* Wv  = (const float*)d_in[3];
    const float* Wo  = (const float*)d_in[4];
    const float* Wg1 = (const float*)d_in[5];
    const float* Wg2 = (const float*)d_in[6];
    const float* bg2 = (const float*)d_in[7];
    const float* gnw = (const float*)d_in[8];
    float* out = (float*)d_out;

    float *pq, *pkv, *poattn, *pwkv, *pwg1p, *pglow;
    cudaGetSymbolAddress((void**)&pq,     g_q);
    cudaGetSymbolAddress((void**)&pkv,    g_kv);
    cudaGetSymbolAddress((void**)&poattn, g_oattn);
    cudaGetSymbolAddress((void**)&pwkv,   g_Wkv);
    cudaGetSymbolAddress((void**)&pwg1p,  g_Wg1p);
    cudaGetSymbolAddress((void**)&pglow,  g_glow);

    static int attr_set = 0;
    if (!attr_set) {
        cudaFuncSetAttribute(phaseC_kernel,
                             cudaFuncAttributeMaxDynamicSharedMemorySize,
                             4 * 64 * PC_LD * 4);
        attr_set = 1;
    }

    concat_w<<<(HID * KVCOLS + 255) / 256, 256>>>(Wk, Wv, Wg1);

    // q = relu(hs @ Wq)
    mma_gemm<<<dim3(QCOLS / GBN, MROWS / GBM), 256>>>(hs, Wq, pq, MROWS, QCOLS, HID, QCOLS);
    // kv = [relu(hs @ Wk) | hs @ Wv]
    mma_gemm<<<dim3(KVCOLS / GBN, MROWS / GBM), 256>>>(hs, pwkv, pkv, MROWS, KVCOLS, HID, 256);
    // glow = hs @ Wg1p (N padded to 128)
    mma_gemm<<<dim3(1, MROWS / GBM), 256>>>(hs, pwg1p, pglow, MROWS, 128, HID, 0);
    // log decays
    gate2_kernel<<<MROWS / 4, 256>>>(Wg2, bg2);
    // chunked GLA
    phaseA_kernel<<<8 * NCHUNK, 64>>>();
    phaseB_kernel<<<64, 128>>>();
    phaseC_kernel<<<8 * 4 * NCHUNK, 256, 4 * 64 * PC_LD * 4>>>(gnw);
    // out = oattn @ Wo
    mma_gemm<<<dim3(HID / GBN, MROWS / GBM), 256>>>(poattn, Wo, out, MROWS, HID, QCOLS, 0);
}

// round 7
// speedup vs baseline: 1.3795x; 1.3795x over previous
#include <cuda_runtime.h>
#include <math.h>

#define BB   2
#define TT   2048
#define HID  1024
#define HH   16
#define HKV  4
#define MROWS  (BB*TT)          // 4096
#define QCOLS  1024
#define KVCOLS 512
#define NCHUNK 32               // T / 64

// ---------------- scratch (device globals; no allocation) ------------------
__device__ float g_hst[MROWS * HID];       // hs rounded to tf32
__device__ float g_q[MROWS * QCOLS];       // relu(hs@Wq)
__device__ float g_kv[MROWS * KVCOLS];     // [relu(hs@Wk)->ke | hs@Wv]
__device__ float g_lg[MROWS * 256];        // log decay -> then be=exp(b)*0.125
__device__ float g_oattn[MROWS * QCOLS];   // normed attention out (tf32-rounded)
__device__ float g_Wkv[HID * KVCOLS];      // concat(Wk, Wv), tf32-rounded
__device__ float g_Wq[HID * QCOLS];        // Wq tf32-rounded
__device__ float g_Wo[QCOLS * HID];        // Wo tf32-rounded
__device__ float g_S[8 * NCHUNK * 64 * 64];// per-chunk entering states
__device__ float g_dl[8 * NCHUNK * 64];    // exp(b_last)

// ---------------- tf32 mma helpers -----------------------------------------
__device__ __forceinline__ unsigned f2tf(float x) {
    unsigned r; asm("cvt.rna.tf32.f32 %0, %1;" : "=r"(r) : "f"(x)); return r;
}
__device__ __forceinline__ float f2tff(float x) {
    return __uint_as_float(f2tf(x));
}
__device__ __forceinline__ void mma_tf32(float* c, const unsigned* a,
                                         unsigned b0, unsigned b1) {
    asm volatile(
        "mma.sync.aligned.m16n8k8.row.col.f32.tf32.tf32.f32 "
        "{%0,%1,%2,%3},{%4,%5,%6,%7},{%8,%9},{%0,%1,%2,%3};"
        : "+f"(c[0]), "+f"(c[1]), "+f"(c[2]), "+f"(c[3])
        : "r"(a[0]), "r"(a[1]), "r"(a[2]), "r"(a[3]), "r"(b0), "r"(b1));
}
__device__ __forceinline__ void cp16(void* smem, const void* g) {
    unsigned s = (unsigned)__cvta_generic_to_shared(smem);
    asm volatile("cp.async.cg.shared.global [%0], [%1], 16;" :: "r"(s), "l"(g) : "memory");
}
__device__ __forceinline__ void cp_commit() {
    asm volatile("cp.async.commit_group;" ::: "memory");
}

// ---------------- cp.async tf32 GEMM: C = act(A @ B), inputs pre-rounded ---
// BM=128, BN=128, BK=32, 3-stage cp.async ring, 256 threads (8 warps 4x2).
#define GLDA 36
#define GLDB 136
#define GSMEM_WORDS (3 * (128 * GLDA + 32 * GLDB))

__global__ void __launch_bounds__(256, 2) mma_gemm(const float* __restrict__ A,
                                                   const float* __restrict__ B,
                                                   float* __restrict__ C,
                                                   int M, int N, int K,
                                                   int relu_limit) {
    extern __shared__ unsigned sm[];
    unsigned (*As)[128][GLDA] = (unsigned(*)[128][GLDA])sm;
    unsigned (*Bs)[32][GLDB]  = (unsigned(*)[32][GLDB])(sm + 3 * 128 * GLDA);

    const int tid  = threadIdx.x;
    const int lane = tid & 31;
    const int warp = tid >> 5;
    const int row0 = blockIdx.y * 128;
    const int col0 = blockIdx.x * 128;
    const int wm = (warp & 3) * 32;
    const int wn = (warp >> 2) * 64;
    const int gr = lane >> 2, gc = lane & 3;

    float acc[2][8][4];
    #pragma unroll
    for (int i = 0; i < 2; i++)
        #pragma unroll
        for (int j = 0; j < 8; j++)
            #pragma unroll
            for (int l = 0; l < 4; l++) acc[i][j][l] = 0.f;

    auto CPA = [&](int kt, int st) {
        const float* ab = A + (size_t)row0 * K + kt * 32;
        #pragma unroll
        for (int i = 0; i < 4; i++) {
            int ch = tid + i * 256;          // 1024 chunks: 128 rows x 8 float4
            int r = ch >> 3, cc = (ch & 7) * 4;
            cp16(&As[st][r][cc], ab + (size_t)r * K + cc);
        }
        const float* bb = B + (size_t)kt * 32 * N + col0;
        #pragma unroll
        for (int i = 0; i < 4; i++) {
            int ch = tid + i * 256;          // 1024 chunks: 32 k x 32 float4
            int kk = ch >> 5, nn = (ch & 31) * 4;
            cp16(&Bs[st][kk][nn], bb + (size_t)kk * N + nn);
        }
        cp_commit();
    };

    auto COMP = [&](int st) {
        #pragma unroll
        for (int ks = 0; ks < 4; ks++) {
            int cb = ks * 8 + gc;
            unsigned a[2][4];
            #pragma unroll
            for (int mt = 0; mt < 2; mt++) {
                int r = wm + mt * 16 + gr;
                a[mt][0] = As[st][r][cb];
                a[mt][1] = As[st][r + 8][cb];
                a[mt][2] = As[st][r][cb + 4];
                a[mt][3] = As[st][r + 8][cb + 4];
            }
            #pragma unroll
            for (int nt = 0; nt < 8; nt++) {
                int nc = wn + nt * 8 + gr;
                unsigned b0 = Bs[st][cb][nc];
                unsigned b1 = Bs[st][cb + 4][nc];
                mma_tf32(acc[0][nt], a[0], b0, b1);
                mma_tf32(acc[1][nt], a[1], b0, b1);
            }
        }
    };

    const int NT = K / 32;
    CPA(0, 0); CPA(1, 1);
    for (int kt = 0; kt < NT; kt++) {
        if (kt + 1 < NT) {
            asm volatile("cp.async.wait_group 1;" ::: "memory");
        } else {
            asm volatile("cp.async.wait_group 0;" ::: "memory");
        }
        __syncthreads();
        if (kt + 2 < NT) CPA(kt + 2, (kt + 2) % 3);
        COMP(kt % 3);
    }

    #pragma unroll
    for (int mt = 0; mt < 2; mt++) {
        #pragma unroll
        for (int nt = 0; nt < 8; nt++) {
            int r  = row0 + wm + mt * 16 + gr;
            int cc = col0 + wn + nt * 8 + gc * 2;
            float v0 = acc[mt][nt][0], v1 = acc[mt][nt][1];
            float v2 = acc[mt][nt][2], v3 = acc[mt][nt][3];
            if (cc < relu_limit) {
                v0 = fmaxf(v0, 0.f); v1 = fmaxf(v1, 0.f);
                v2 = fmaxf(v2, 0.f); v3 = fmaxf(v3, 0.f);
            }
            *(float2*)&C[(size_t)r * N + cc]       = make_float2(v0, v1);
            *(float2*)&C[(size_t)(r + 8) * N + cc] = make_float2(v2, v3);
        }
    }
}

// ---------------- prep: round weights/activations to tf32 ------------------
__global__ void prep_w(const float* __restrict__ Wq, const float* __restrict__ Wk,
                       const float* __restrict__ Wv, const float* __restrict__ Wo) {
    int i = blockIdx.x * 256 + threadIdx.x;   // over 1M
    g_Wq[i] = f2tff(Wq[i]);
    g_Wo[i] = f2tff(Wo[i]);
    if (i < HID * KVCOLS) {
        int k = i >> 9, n = i & 511;
        g_Wkv[i] = f2tff((n < 256) ? Wk[k * 256 + n] : Wv[k * 256 + n - 256]);
    }
}
__global__ void conv_hs(const float* __restrict__ hs) {
    int i = blockIdx.x * 256 + threadIdx.x;   // over 1M float4
    float4 v = ((const float4*)hs)[i];
    ((float4*)g_hst)[i] = make_float4(f2tff(v.x), f2tff(v.y), f2tff(v.z), f2tff(v.w));
}

// ---------------- fused gate: lg = logsigmoid((hs@Wg1)@Wg2 + b)/16 ---------
// 128 blocks x 32 rows, 256 threads. Wg1/Wg2 tiles staged in smem.
__global__ void __launch_bounds__(256) gate_fused(const float* __restrict__ hs,
                                                  const float* __restrict__ Wg1,
                                                  const float* __restrict__ Wg2,
                                                  const float* __restrict__ bg2) {
    __shared__ float hs_s[32][128];
    __shared__ float w1_s[128][16];
    __shared__ float glow_s[32][16];
    __shared__ float w2_s[16][256];

    const int tid = threadIdx.x;
    const int row0 = blockIdx.x * 32;
    const int rowA = tid >> 4;      // 0..15 -> rows rowA, rowA+16
    const int col  = tid & 15;

    #pragma unroll
    for (int i = tid; i < 4096; i += 256)
        w2_s[i >> 8][i & 255] = Wg2[i];

    float acc0 = 0.f, acc1 = 0.f;
    for (int kt = 0; kt < 8; kt++) {
        __syncthreads();
        // 32 rows x 128 cols = 1024 float4, 32 float4 per row
        #pragma unroll
        for (int i = 0; i < 4; i++) {
            int ch = tid + i * 256;
            int r = ch >> 5, cc = (ch & 31) * 4;
            *(float4*)&hs_s[r][cc] = *(const float4*)&hs[(size_t)(row0 + r) * HID + kt * 128 + cc];
        }
        // 128 k x 16 cols = 512 float4, 4 float4 per row
        #pragma unroll
        for (int i = 0; i < 2; i++) {
            int ch = tid + i * 256;
            int kk = ch >> 2, cc = (ch & 3) * 4;
            *(float4*)&w1_s[kk][cc] = *(const float4*)&Wg1[(size_t)(kt * 128 + kk) * 16 + cc];
        }
        __syncthreads();
        #pragma unroll 8
        for (int k = 0; k < 128; k++) {
            float w = w1_s[k][col];
            acc0 = fmaf(hs_s[rowA][k], w, acc0);
            acc1 = fmaf(hs_s[rowA + 16][k], w, acc1);
        }
    }
    glow_s[rowA][col]      = acc0;
    glow_s[rowA + 16][col] = acc1;
    __syncthreads();

    const int c = tid;
    const float bias = bg2[c];
    #pragma unroll 4
    for (int r = 0; r < 32; r++) {
        float x = bias;
        #pragma unroll
        for (int j = 0; j < 16; j++) x = fmaf(glow_s[r][j], w2_s[j][c], x);
        float ls = fminf(x, 0.f) - log1pf(__expf(-fabsf(x)));
        g_lg[(size_t)(row0 + r) * 256 + c] = ls * 0.0625f;
    }
}

// ---------------- Phase A: cumsum; be=exp(b)/8 in place; scale k -----------
__global__ void __launch_bounds__(64) phaseA_kernel() {
    const int c   = blockIdx.x & 31;
    const int grp = blockIdx.x >> 5;
    const int b = grp >> 2, hk = grp & 3;
    const int d = threadIdx.x;
    float bacc = 0.f;
    const size_t row0 = (size_t)b * TT + c * 64;
    for (int t = 0; t < 64; t++) {
        const size_t r = row0 + t;
        bacc += g_lg[r * 256 + hk * 64 + d];
        g_lg[r * 256 + hk * 64 + d] = __expf(bacc) * 0.125f;
        g_kv[r * 512 + hk * 64 + d] *= __expf(-bacc);
    }
    g_dl[(grp * 32 + c) * 64 + d] = __expf(bacc);
}

// ---------------- Phase B: propagate states across chunks ------------------
__global__ void __launch_bounds__(128) phaseB_kernel() {
    const int grp = blockIdx.x >> 3;
    const int vc  = blockIdx.x & 7;
    const int b = grp >> 2, hk = grp & 3;
    const int tid = threadIdx.x;
    const int v  = tid & 7;
    const int kg = tid >> 3;
    __shared__ float ke_s[64][64];
    __shared__ float v_s[64][8];
    float S0 = 0.f, S1 = 0.f, S2 = 0.f, S3 = 0.f;

    for (int c = 0; c < NCHUNK; c++) {
        const size_t row0 = (size_t)b * TT + c * 64;
        __syncthreads();
        #pragma unroll
        for (int i = tid; i < 64 * 16; i += 128) {
            int t = i >> 4, dq = i & 15;
            ((float4*)ke_s[t])[dq] = *(const float4*)&g_kv[(row0 + t) * 512 + hk * 64 + dq * 4];
        }
        {
            int t = tid >> 1, q4 = tid & 1;
            ((float4*)v_s[t])[q4] = *(const float4*)&g_kv[(row0 + t) * 512 + 256 + hk * 64 + vc * 8 + q4 * 4];
        }
        __syncthreads();

        const size_t sb_ = ((size_t)(grp * 32 + c) * 64 + kg * 4) * 64 + vc * 8 + v;
        g_S[sb_]       = S0;
        g_S[sb_ + 64]  = S1;
        g_S[sb_ + 128] = S2;
        g_S[sb_ + 192] = S3;

        #pragma unroll 4
        for (int t = 0; t < 64; t++) {
            const float4 kk = ((const float4*)ke_s[t])[kg];
            const float  vv = v_s[t][v];
            S0 = fmaf(kk.x, vv, S0);
            S1 = fmaf(kk.y, vv, S1);
            S2 = fmaf(kk.z, vv, S2);
            S3 = fmaf(kk.w, vv, S3);
        }
        const float4 dl4 = *(const float4*)&g_dl[(grp * 32 + c) * 64 + kg * 4];
        S0 *= dl4.x; S1 *= dl4.y; S2 *= dl4.z; S3 *= dl4.w;
    }
}

// ---------------- Phase C: tensor-core intra-chunk + inter + RMSNorm -------
#define PC_LD 65
__global__ void __launch_bounds__(256) phaseC_kernel(const float* __restrict__ gnw) {
    extern __shared__ unsigned smc[];
    unsigned* qe  = smc;
    unsigned* keT = smc + 64 * PC_LD;
    unsigned* vs  = smc + 2 * 64 * PC_LD;
    unsigned* Ss  = smc + 3 * 64 * PC_LD;
    __shared__ float rs[64][2];

    const int c   = blockIdx.x & 31;
    const int h   = (blockIdx.x >> 5) & 3;
    const int grp = blockIdx.x >> 7;
    const int b = grp >> 2, hk = grp & 3;
    const int tid  = threadIdx.x;
    const int lane = tid & 31;
    const int warp = tid >> 5;
    const int wm = (warp & 3) * 16;
    const int wn = (warp >> 2) * 32;
    const int gr = lane >> 2, gc = lane & 3;
    const size_t row0 = (size_t)b * TT + c * 64;

    for (int i = tid; i < 4096; i += 256) {
        int t = i >> 6, d = i & 63;
        float qv = g_q[(row0 + t) * 1024 + hk * 256 + h * 64 + d]
                 * g_lg[(row0 + t) * 256 + hk * 64 + d];
        qe [t * PC_LD + d] = f2tf(qv);
        keT[d * PC_LD + t] = f2tf(g_kv[(row0 + t) * 512 + hk * 64 + d]);
        vs [t * PC_LD + d] = f2tf(g_kv[(row0 + t) * 512 + 256 + hk * 64 + d]);
        Ss [t * PC_LD + d] = f2tf(g_S[((size_t)(grp * 32 + c) * 64 + t) * 64 + d]);
    }
    __syncthreads();

    float accA[4][4];
    #pragma unroll
    for (int j = 0; j < 4; j++)
        #pragma unroll
        for (int l = 0; l < 4; l++) accA[j][l] = 0.f;
    const int rm = wm + gr;
    #pragma unroll
    for (int ks = 0; ks < 8; ks++) {
        int cb = ks * 8 + gc;
        unsigned a[4];
        a[0] = qe[rm * PC_LD + cb];
        a[1] = qe[(rm + 8) * PC_LD + cb];
        a[2] = qe[rm * PC_LD + cb + 4];
        a[3] = qe[(rm + 8) * PC_LD + cb + 4];
        #pragma unroll
        for (int nt = 0; nt < 4; nt++) {
            int nc = wn + nt * 8 + gr;
            unsigned b0 = keT[cb * PC_LD + nc];
            unsigned b1 = keT[(cb + 4) * PC_LD + nc];
            mma_tf32(accA[nt], a, b0, b1);
        }
    }
    __syncthreads();
    #pragma unroll
    for (int nt = 0; nt < 4; nt++) {
        int s0 = wn + nt * 8 + gc * 2;
        keT[rm * PC_LD + s0]           = f2tf(s0     <= rm     ? accA[nt][0] : 0.f);
        keT[rm * PC_LD + s0 + 1]       = f2tf(s0 + 1 <= rm     ? accA[nt][1] : 0.f);
        keT[(rm + 8) * PC_LD + s0]     = f2tf(s0     <= rm + 8 ? accA[nt][2] : 0.f);
        keT[(rm + 8) * PC_LD + s0 + 1] = f2tf(s0 + 1 <= rm + 8 ? accA[nt][3] : 0.f);
    }
    __syncthreads();

    float acc[4][4];
    #pragma unroll
    for (int j = 0; j < 4; j++)
        #pragma unroll
        for (int l = 0; l < 4; l++) acc[j][l] = 0.f;
    #pragma unroll
    for (int ks = 0; ks < 8; ks++) {
        int cb = ks * 8 + gc;
        unsigned a[4];
        a[0] = keT[rm * PC_LD + cb];
        a[1] = keT[(rm + 8) * PC_LD + cb];
        a[2] = keT[rm * PC_LD + cb + 4];
        a[3] = keT[(rm + 8) * PC_LD + cb + 4];
        #pragma unroll
        for (int nt = 0; nt < 4; nt++) {
            int nc = wn + nt * 8 + gr;
            unsigned b0 = vs[cb * PC_LD + nc];
            unsigned b1 = vs[(cb + 4) * PC_LD + nc];
            mma_tf32(acc[nt], a, b0, b1);
        }
    }
    #pragma unroll
    for (int ks = 0; ks < 8; ks++) {
        int cb = ks * 8 + gc;
        unsigned a[4];
        a[0] = qe[rm * PC_LD + cb];
        a[1] = qe[(rm + 8) * PC_LD + cb];
        a[2] = qe[rm * PC_LD + cb + 4];
        a[3] = qe[(rm + 8) * PC_LD + cb + 4];
        #pragma unroll
        for (int nt = 0; nt < 4; nt++) {
            int nc = wn + nt * 8 + gr;
            unsigned b0 = Ss[cb * PC_LD + nc];
            unsigned b1 = Ss[(cb + 4) * PC_LD + nc];
            mma_tf32(acc[nt], a, b0, b1);
        }
    }

    float ss0 = 0.f, ss1 = 0.f;
    #pragma unroll
    for (int nt = 0; nt < 4; nt++) {
        ss0 += acc[nt][0] * acc[nt][0] + acc[nt][1] * acc[nt][1];
        ss1 += acc[nt][2] * acc[nt][2] + acc[nt][3] * acc[nt][3];
    }
    ss0 += __shfl_xor_sync(0xffffffffu, ss0, 1);
    ss0 += __shfl_xor_sync(0xffffffffu, ss0, 2);
    ss1 += __shfl_xor_sync(0xffffffffu, ss1, 1);
    ss1 += __shfl_xor_sync(0xffffffffu, ss1, 2);
    if (gc == 0) {
        rs[rm][warp >> 2]     = ss0;
        rs[rm + 8][warp >> 2] = ss1;
    }
    __syncthreads();
    float r0 = rsqrtf((rs[rm][0] + rs[rm][1]) * (1.f / 64.f) + 1e-6f);
    float r1 = rsqrtf((rs[rm + 8][0] + rs[rm + 8][1]) * (1.f / 64.f) + 1e-6f);

    const size_t ob = (row0)*1024 + (size_t)(hk * 4 + h) * 64;
    #pragma unroll
    for (int nt = 0; nt < 4; nt++) {
        int cc = wn + nt * 8 + gc * 2;
        float gw0 = gnw[cc], gw1 = gnw[cc + 1];
        *(float2*)&g_oattn[ob + (size_t)rm * 1024 + cc] =
            make_float2(f2tff(acc[nt][0] * r0 * gw0), f2tff(acc[nt][1] * r0 * gw1));
        *(float2*)&g_oattn[ob + (size_t)(rm + 8) * 1024 + cc] =
            make_float2(f2tff(acc[nt][2] * r1 * gw0), f2tff(acc[nt][3] * r1 * gw1));
    }
}

// ---------------- launch -----------------------------------------------------
extern "C" void kernel_launch(void* const* d_in, const int* in_sizes, int n_in,
                              void* d_out, int out_size) {
    const float* hs  = (const float*)d_in[0];
    const float* Wq  = (const float*)d_in[1];
    const float* Wk  = (const float*)d_in[2];
    const float* Wv  = (const float*)d_in[3];
    const float* Wo  = (const float*)d_in[4];
    const float* Wg1 = (const float*)d_in[5];
    const float* Wg2 = (const float*)d_in[6];
    const float* bg2 = (const float*)d_in[7];
    const float* gnw = (const float*)d_in[8];
    float* out = (float*)d_out;

    float *phst, *pq, *pkv, *poattn, *pwkv, *pwq, *pwo;
    cudaGetSymbolAddress((void**)&phst,   g_hst);
    cudaGetSymbolAddress((void**)&pq,     g_q);
    cudaGetSymbolAddress((void**)&pkv,    g_kv);
    cudaGetSymbolAddress((void**)&poattn, g_oattn);
    cudaGetSymbolAddress((void**)&pwkv,   g_Wkv);
    cudaGetSymbolAddress((void**)&pwq,    g_Wq);
    cudaGetSymbolAddress((void**)&pwo,    g_Wo);

    cudaFuncSetAttribute(phaseC_kernel,
                         cudaFuncAttributeMaxDynamicSharedMemorySize,
                         4 * 64 * PC_LD * 4);
    cudaFuncSetAttribute(mma_gemm,
                         cudaFuncAttributeMaxDynamicSharedMemorySize,
                         GSMEM_WORDS * 4);
    const int gsmem = GSMEM_WORDS * 4;

    // prep: tf32-round inputs/weights
    prep_w<<<(HID * QCOLS) / 256, 256>>>(Wq, Wk, Wv, Wo);
    conv_hs<<<(MROWS * HID / 4) / 256, 256>>>(hs);
    // fused gate (fp32 direct from hs)
    gate_fused<<<MROWS / 32, 256>>>(hs, Wg1, Wg2, bg2);

    // q = relu(hs @ Wq)
    mma_gemm<<<dim3(QCOLS / 128, MROWS / 128), 256, gsmem>>>(phst, pwq, pq, MROWS, QCOLS, HID, QCOLS);
    // kv = [relu(hs @ Wk) | hs @ Wv]
    mma_gemm<<<dim3(KVCOLS / 128, MROWS / 128), 256, gsmem>>>(phst, pwkv, pkv, MROWS, KVCOLS, HID, 256);

    // chunked GLA
    phaseA_kernel<<<8 * NCHUNK, 64>>>();
    phaseB_kernel<<<64, 128>>>();
    phaseC_kernel<<<8 * 4 * NCHUNK, 256, 4 * 64 * PC_LD * 4>>>(gnw);

    // out = oattn @ Wo
    mma_gemm<<<dim3(HID / 128, MROWS / 128), 256, gsmem>>>(poattn, pwo, out, MROWS, HID, QCOLS, 0);
}